// round 5
// baseline (speedup 1.0000x reference)
#include <cuda_runtime.h>
#include <cuda_bf16.h>

// Fixed problem shape: x[2, B, N] fp32, N=1024, B=32768.
#define NDIM 1024
#define THREADS 256
#define JPT 4            // output columns per thread (THREADS*JPT == NDIM)
#define ROWS 8           // batch rows per block

// Per-output-column fused tables (filled by prep_kernel):
//   g_idx[j]  = (srcA, srcB) = (L[R[j]], L[P[R[j]]])
//   g_coef[j] = (diag_r[k], diag_i[k], off_r[p], off_i[p]) with k=R[j], p=P[k]
__device__ int2   g_idx[NDIM];
__device__ float4 g_coef[NDIM];

__global__ void prep_kernel(const float* __restrict__ diag,
                            const float* __restrict__ off_diag,
                            const int* __restrict__ pperm,
                            const int* __restrict__ lperm,
                            const int* __restrict__ rperm,
                            int n) {
    int j = blockIdx.x * blockDim.x + threadIdx.x;
    if (j < n) {
        int k = rperm[j];
        int p = pperm[k];
        g_idx[j]  = make_int2(lperm[k], lperm[p]);
        g_coef[j] = make_float4(diag[k], diag[n + k], off_diag[p], off_diag[n + p]);
    }
}

__global__ void __launch_bounds__(THREADS)
mesh_kernel(const float* __restrict__ x, float* __restrict__ out, int B) {
    __shared__ float2 s[2][NDIM];   // interleaved (re, im) row, double-buffered

    const int t  = threadIdx.x;
    const int j0 = t * JPT;

    // Pull this thread's fused tables into registers (tiny, L1/L2-resident).
    int2   idx[JPT];
    float4 cf[JPT];
#pragma unroll
    for (int u = 0; u < JPT; u++) { idx[u] = g_idx[j0 + u]; cf[u] = g_coef[j0 + u]; }

    const long long planes = (long long)B * NDIM;
    const float4* xr4 = (const float4*)x;
    const float4* xi4 = (const float4*)(x + planes);
    float4* or4 = (float4*)out;
    float4* oi4 = (float4*)(out + planes);

    const int RW4 = NDIM / 4;                       // float4s per row
    const long long row0 = (long long)blockIdx.x * ROWS;
    const int nrows = (row0 + ROWS <= B) ? ROWS : (int)(B - row0);
    if (nrows <= 0) return;

    long long base = row0 * RW4 + t;

    // Prefetch row 0 (coalesced 128-bit loads).
    float4 curR = xr4[base];
    float4 curI = xi4[base];

    for (int r = 0; r < nrows; r++) {
        float2* sb = s[r & 1];
        // Stage current row into smem, interleaved for LDS.64 gathers.
        sb[j0 + 0] = make_float2(curR.x, curI.x);
        sb[j0 + 1] = make_float2(curR.y, curI.y);
        sb[j0 + 2] = make_float2(curR.z, curI.z);
        sb[j0 + 3] = make_float2(curR.w, curI.w);
        // Issue next row's loads BEFORE the barrier: DRAM latency overlaps
        // the sync + gather + compute of this row.
        if (r + 1 < nrows) {
            long long nb = base + (long long)(r + 1) * RW4;
            curR = xr4[nb];
            curI = xi4[nb];
        }
        __syncthreads();

        float4 outR, outI;
        float* pR = &outR.x;
        float* pI = &outI.x;
#pragma unroll
        for (int u = 0; u < JPT; u++) {
            float2 a = sb[idx[u].x];   // column L[k]
            float2 b = sb[idx[u].y];   // column L[p]
            float4 c = cf[u];
            pR[u] = a.x * c.x - a.y * c.y + b.x * c.z - b.y * c.w;
            pI[u] = a.x * c.y + a.y * c.x + b.x * c.w + b.y * c.z;
        }
        long long ob = (row0 + r) * RW4 + t;
        or4[ob] = outR;   // STG.128, fully coalesced
        oi4[ob] = outI;
        // No second barrier needed: double buffer + next iteration's sync
        // separates this row's reads from the r+2 rewrite of this buffer.
    }
}

extern "C" void kernel_launch(void* const* d_in, const int* in_sizes, int n_in,
                              void* d_out, int out_size) {
    const float* x        = (const float*)d_in[0];   // [2, B, N] fp32
    const float* diag     = (const float*)d_in[1];   // [2, N]
    const float* off_diag = (const float*)d_in[2];   // [2, N]
    const int*   pperm    = (const int*)d_in[3];     // [N]
    const int*   lperm    = (const int*)d_in[4];     // [N]
    const int*   rperm    = (const int*)d_in[5];     // [N]
    float* out = (float*)d_out;

    const int n = in_sizes[1] / 2;                   // N (== NDIM)
    const int B = in_sizes[0] / (2 * n);

    prep_kernel<<<(n + 255) / 256, 256>>>(diag, off_diag, pperm, lperm, rperm, n);

    int grid = (B + ROWS - 1) / ROWS;
    mesh_kernel<<<grid, THREADS>>>(x, out, B);
}

// round 7
// speedup vs baseline: 1.1550x; 1.1550x over previous
#include <cuda_runtime.h>
#include <cuda_bf16.h>

// Fixed problem shape: x[2, B, N] fp32, N=1024, B=32768.
#define NDIM 1024
#define THREADS 256
#define JPT 4            // output columns per thread (THREADS*JPT == NDIM)
#define RPI 2            // rows staged per barrier
#define ROWS 16          // batch rows per block
#define ITERS (ROWS / RPI)
#define SLOTS (NDIM / 2) // float4 slots per staged row (each holds 2 float2 cols)

// Swizzle at float4-slot granularity: phys = l ^ ((l>>3)&7).
// Bijection on [0,512): XORs bits0..2 with bits3..5 -> always in bounds.
// Per 8-lane STS.128 phase (lanes r0..r0+7, slots 2r / 2r+1), residues mod 8
// are ((r&3)<<1) ^ ((r>>2)&1 in bit0, ...) -> all distinct -> conflict-free.
__device__ __forceinline__ int slot_swz(int l) { return l ^ ((l >> 3) & 7); }
// float2 column c -> swizzled float2 index
__device__ __forceinline__ int col_swz(int c) { return 2 * slot_swz(c >> 1) + (c & 1); }

__global__ void __launch_bounds__(THREADS)
mesh_kernel(const float* __restrict__ x, float* __restrict__ out,
            const float* __restrict__ diag, const float* __restrict__ off_diag,
            const int* __restrict__ pperm, const int* __restrict__ lperm,
            const int* __restrict__ rperm, int B) {
    __shared__ float2 s[2][RPI][NDIM];   // 32 KB, double-buffered 2-row stages

    const int t = threadIdx.x;

    const long long planes = (long long)B * NDIM;
    const float4* xr4 = (const float4*)x;
    const float4* xi4 = (const float4*)(x + planes);
    float4* or4 = (float4*)out;
    float4* oi4 = (float4*)(out + planes);

    const int RW4 = NDIM / 4;
    const long long row0 = (long long)blockIdx.x * ROWS;
    const long long base = row0 * RW4 + t;

    // ---- issue first 2-row prefetch immediately (4 independent LDG.128) ----
    float4 curR[RPI], curI[RPI];
#pragma unroll
    for (int v = 0; v < RPI; v++) {
        long long a = base + (long long)v * RW4;
        if (row0 + v < B) { curR[v] = xr4[a]; curI[v] = xi4[a]; }
    }

    // ---- per-thread fused tables (overlaps the prefetch latency) ----
    // Output column j: k=R[j], p=P[k]; sources x[:, L[k]], x[:, L[p]];
    // coefs (diag_r[k], diag_i[k], off_r[p], off_i[p]). Indices pre-swizzled.
    int    ia[JPT], ib[JPT];
    float4 cf[JPT];
    {
        int4 kk = ((const int4*)rperm)[t];       // rperm[4t..4t+3], coalesced
        int karr[4] = {kk.x, kk.y, kk.z, kk.w};
#pragma unroll
        for (int u = 0; u < JPT; u++) {
            int k = karr[u];
            int p = pperm[k];
            ia[u] = col_swz(lperm[k]);
            ib[u] = col_swz(lperm[p]);
            cf[u] = make_float4(diag[k], diag[NDIM + k],
                                off_diag[p], off_diag[NDIM + p]);
        }
    }

    // This thread owns logical float4 slots 2t and 2t+1 (columns 4t..4t+3).
    const int sl0 = slot_swz(2 * t);
    const int sl1 = slot_swz(2 * t + 1);

    for (int it = 0; it < ITERS; it++) {
        float2 (*sb)[NDIM] = s[it & 1];

        // Stage current 2 rows (conflict-free swizzled STS.128).
#pragma unroll
        for (int v = 0; v < RPI; v++) {
            float4* sv = (float4*)(&sb[v][0]);
            sv[sl0] = make_float4(curR[v].x, curI[v].x, curR[v].y, curI[v].y);
            sv[sl1] = make_float4(curR[v].z, curI[v].z, curR[v].w, curI[v].w);
        }

        // Issue next 2 rows' loads BEFORE the barrier: DRAM latency overlaps
        // the sync + gather + compute of this stage.
        if (it + 1 < ITERS) {
            long long nb = base + (long long)(it + 1) * RPI * RW4;
#pragma unroll
            for (int v = 0; v < RPI; v++) {
                long long a = nb + (long long)v * RW4;
                if (row0 + (long long)(it + 1) * RPI + v < B) {
                    curR[v] = xr4[a]; curI[v] = xi4[a];
                }
            }
        }
        __syncthreads();

        // Gather + complex MAC + coalesced 128-bit stores, per staged row.
#pragma unroll
        for (int v = 0; v < RPI; v++) {
            long long row = row0 + (long long)it * RPI + v;
            if (row >= B) break;
            const float2* sr = &sb[v][0];
            float4 outR, outI;
            float* pR = &outR.x;
            float* pI = &outI.x;
#pragma unroll
            for (int u = 0; u < JPT; u++) {
                float2 a = sr[ia[u]];      // column L[k]   (LDS.64)
                float2 b = sr[ib[u]];      // column L[p]   (LDS.64)
                float4 c = cf[u];
                pR[u] = a.x * c.x - a.y * c.y + b.x * c.z - b.y * c.w;
                pI[u] = a.x * c.y + a.y * c.x + b.x * c.w + b.y * c.z;
            }
            long long ob = row * RW4 + t;
            or4[ob] = outR;                // STG.128, fully coalesced
            oi4[ob] = outI;
        }
        // No trailing barrier: reads of buffer (it&1) complete before the
        // sync in iter it+1, and that buffer is only rewritten in iter it+2.
    }
}

extern "C" void kernel_launch(void* const* d_in, const int* in_sizes, int n_in,
                              void* d_out, int out_size) {
    const float* x        = (const float*)d_in[0];   // [2, B, N] fp32
    const float* diag     = (const float*)d_in[1];   // [2, N]
    const float* off_diag = (const float*)d_in[2];   // [2, N]
    const int*   pperm    = (const int*)d_in[3];     // [N]
    const int*   lperm    = (const int*)d_in[4];     // [N]
    const int*   rperm    = (const int*)d_in[5];     // [N]
    float* out = (float*)d_out;

    const int n = in_sizes[1] / 2;                   // N (== NDIM)
    const int B = in_sizes[0] / (2 * n);

    int grid = (B + ROWS - 1) / ROWS;
    mesh_kernel<<<grid, THREADS>>>(x, out, diag, off_diag,
                                   pperm, lperm, rperm, B);
}

// round 8
// speedup vs baseline: 1.2109x; 1.0484x over previous
#include <cuda_runtime.h>
#include <cuda_bf16.h>

// Fixed problem shape: x[2, B, N] fp32, N=1024, B=32768.
#define NDIM 1024
#define THREADS 256
#define JPT 4            // output columns per thread (THREADS*JPT == NDIM)
#define RPI 2            // rows staged per pipeline stage
#define ROWS 32          // batch rows per block
#define ITERS (ROWS / RPI)

__device__ __forceinline__ void cp_async16(void* dst_smem, const void* src_gmem) {
    unsigned s = (unsigned)__cvta_generic_to_shared(dst_smem);
    asm volatile("cp.async.cg.shared.global [%0], [%1], 16;" :: "r"(s), "l"(src_gmem));
}
__device__ __forceinline__ void cp_commit()   { asm volatile("cp.async.commit_group;"); }
__device__ __forceinline__ void cp_wait_all() { asm volatile("cp.async.wait_group 0;" ::: "memory"); }

__global__ void __launch_bounds__(THREADS, 4)
mesh_kernel(const float* __restrict__ x, float* __restrict__ out,
            const float* __restrict__ diag, const float* __restrict__ off_diag,
            const int* __restrict__ pperm, const int* __restrict__ lperm,
            const int* __restrict__ rperm, int B) {
    // Split-plane staging (cp.async preserves GMEM layout): 32 KB total.
    __shared__ float sre[2][RPI][NDIM];
    __shared__ float sim[2][RPI][NDIM];

    const int t  = threadIdx.x;
    const int c0 = 4 * t;                       // this thread's staging chunk
    const unsigned planes = (unsigned)B * NDIM; // 33.5M elements: fits 32-bit
    const float* xr = x;
    const float* xi = x + planes;

    const int row0 = (int)blockIdx.x * ROWS;

    // ---- prologue: stage first 2 rows into buffer 0 (async, no registers) ----
#pragma unroll
    for (int v = 0; v < RPI; v++) {
        int row = min(row0 + v, B - 1);
        unsigned off = (unsigned)row * NDIM + c0;
        cp_async16(&sre[0][v][c0], xr + off);
        cp_async16(&sim[0][v][c0], xi + off);
    }
    cp_commit();

    // ---- per-thread fused tables (global loads overlap prologue copies) ----
    // Output column j: k=R[j], p=P[k]; sources x[:, L[k]], x[:, L[p]];
    // coefs (diag_r[k], diag_i[k], off_r[p], off_i[p]).
    int    ia[JPT], ib[JPT];
    float4 cf[JPT];
    {
        int4 kk = ((const int4*)rperm)[t];      // rperm[4t..4t+3], coalesced
        int karr[4] = {kk.x, kk.y, kk.z, kk.w};
#pragma unroll
        for (int u = 0; u < JPT; u++) {
            int k = karr[u];
            int p = pperm[k];
            ia[u] = lperm[k];
            ib[u] = lperm[p];
            cf[u] = make_float4(diag[k], diag[NDIM + k],
                                off_diag[p], off_diag[NDIM + p]);
        }
    }

    float4* or4 = (float4*)out;
    float4* oi4 = (float4*)(out + planes);

    for (int it = 0; it < ITERS; it++) {
        // Buffer it&1 was filled by the single outstanding copy group.
        cp_wait_all();
        __syncthreads();   // copies visible to all; everyone left iter it-1

        // Issue next stage's copies AFTER the barrier: previous readers of
        // buffer (it+1)&1 (iter it-1) are provably done. Copies overlap the
        // gather/compute/store below.
        if (it + 1 < ITERS) {
            int rb = row0 + (it + 1) * RPI;
#pragma unroll
            for (int v = 0; v < RPI; v++) {
                int row = min(rb + v, B - 1);
                unsigned off = (unsigned)row * NDIM + c0;
                cp_async16(&sre[(it + 1) & 1][v][c0], xr + off);
                cp_async16(&sim[(it + 1) & 1][v][c0], xi + off);
            }
            cp_commit();
        }

        const float (*rr)[NDIM] = sre[it & 1];
        const float (*mm)[NDIM] = sim[it & 1];
#pragma unroll
        for (int v = 0; v < RPI; v++) {
            int row = row0 + it * RPI + v;
            if (row >= B) break;               // uniform per block
            const float* r_ = rr[v];
            const float* m_ = mm[v];
            float4 outR, outI;
            float* pR = &outR.x;
            float* pI = &outI.x;
#pragma unroll
            for (int u = 0; u < JPT; u++) {
                float aR = r_[ia[u]], aI = m_[ia[u]];   // LDS.32 pair, col L[k]
                float bR = r_[ib[u]], bI = m_[ib[u]];   // LDS.32 pair, col L[p]
                float4 c = cf[u];
                pR[u] = aR * c.x - aI * c.y + bR * c.z - bI * c.w;
                pI[u] = aR * c.y + aI * c.x + bR * c.w + bI * c.z;
            }
            unsigned ob = (unsigned)row * (NDIM / 4) + t;
            or4[ob] = outR;                    // STG.128, fully coalesced
            oi4[ob] = outI;
        }
    }
}

extern "C" void kernel_launch(void* const* d_in, const int* in_sizes, int n_in,
                              void* d_out, int out_size) {
    const float* x        = (const float*)d_in[0];   // [2, B, N] fp32
    const float* diag     = (const float*)d_in[1];   // [2, N]
    const float* off_diag = (const float*)d_in[2];   // [2, N]
    const int*   pperm    = (const int*)d_in[3];     // [N]
    const int*   lperm    = (const int*)d_in[4];     // [N]
    const int*   rperm    = (const int*)d_in[5];     // [N]
    float* out = (float*)d_out;

    const int n = in_sizes[1] / 2;                   // N (== NDIM)
    const int B = in_sizes[0] / (2 * n);

    int grid = (B + ROWS - 1) / ROWS;
    mesh_kernel<<<grid, THREADS>>>(x, out, diag, off_diag,
                                   pperm, lperm, rperm, B);
}

// round 12
// speedup vs baseline: 1.2165x; 1.0046x over previous
#include <cuda_runtime.h>
#include <cuda_bf16.h>

// Fixed problem shape: x[2, B, N] fp32, N=1024, B=32768.
#define NDIM 1024
#define THREADS 512
#define JPT 2            // output columns per thread (THREADS*JPT == NDIM)
#define RPI 2            // rows staged per pipeline stage
#define ROWS 32          // batch rows per block
#define ITERS (ROWS / RPI)
#define STAGES 3

__device__ __forceinline__ void cp_async16(void* dst_smem, const void* src_gmem) {
    unsigned s = (unsigned)__cvta_generic_to_shared(dst_smem);
    asm volatile("cp.async.cg.shared.global [%0], [%1], 16;" :: "r"(s), "l"(src_gmem));
}
__device__ __forceinline__ void cp_commit()  { asm volatile("cp.async.commit_group;"); }
__device__ __forceinline__ void cp_wait1()   { asm volatile("cp.async.wait_group 1;" ::: "memory"); }

__global__ void __launch_bounds__(THREADS, 3)
mesh_kernel(const float* __restrict__ x, float* __restrict__ out,
            const float* __restrict__ diag, const float* __restrict__ off_diag,
            const int* __restrict__ pperm, const int* __restrict__ lperm,
            const int* __restrict__ rperm, int B) {
    // Split-plane staging, 3-stage pipeline: 48 KB total.
    __shared__ float sre[STAGES][RPI][NDIM];
    __shared__ float sim[STAGES][RPI][NDIM];

    const int t = threadIdx.x;
    const unsigned planes = (unsigned)B * NDIM;   // 33.5M: fits 32-bit
    const float* xr = x;
    const float* xi = x + planes;

    const int row0 = (int)blockIdx.x * ROWS;
    // Staging assignment: thread covers row (t>>8) of the stage, cols 4*(t&255).
    const int sv = t >> 8;
    const int sc = (t & 255) * 4;

    // ---- prologue: issue stages 0 and 1 as separate groups ----
#pragma unroll
    for (int s = 0; s < 2; s++) {
        int row = min(row0 + s * RPI + sv, B - 1);
        unsigned off = (unsigned)row * NDIM + sc;
        cp_async16(&sre[s][sv][sc], xr + off);
        cp_async16(&sim[s][sv][sc], xi + off);
        cp_commit();
    }

    // ---- per-thread fused tables (overlap the prologue copies) ----
    // Output column j: k=R[j], p=P[k]; sources x[:, L[k]], x[:, L[p]];
    // coefs (diag_r[k], diag_i[k], off_r[p], off_i[p]).
    // Indices packed: pk[u] = L[k] | (L[p] << 16).
    int    pk[JPT];
    float4 cf[JPT];
    {
        int2 kk = ((const int2*)rperm)[t];        // rperm[2t], rperm[2t+1]
        int karr[2] = {kk.x, kk.y};
#pragma unroll
        for (int u = 0; u < JPT; u++) {
            int k = karr[u];
            int p = pperm[k];
            pk[u] = lperm[k] | (lperm[p] << 16);
            cf[u] = make_float4(diag[k], diag[NDIM + k],
                                off_diag[p], off_diag[NDIM + p]);
        }
    }

    float2* or2 = (float2*)out;
    float2* oi2 = (float2*)(out + planes);

    for (int it = 0; it < ITERS; it++) {
        // Buffer it%3's group is always exactly 2 commits behind the head
        // (we commit unconditionally below), so wait ≤1 pending guarantees it.
        cp_wait1();
        __syncthreads();   // copies visible to all; all threads left iter it-1

        // Issue stage it+2 AFTER the barrier: readers of buffer (it+2)%3
        // (iter it-1) are provably done. Copies overlap ~2 compute stages.
        if (it + 2 < ITERS) {
            int row = min(row0 + (it + 2) * RPI + sv, B - 1);
            unsigned off = (unsigned)row * NDIM + sc;
            int b = (it + 2) % STAGES;
            cp_async16(&sre[b][sv][sc], xr + off);
            cp_async16(&sim[b][sv][sc], xi + off);
        }
        // UNCONDITIONAL commit: during the drain (it+2 >= ITERS) this pushes an
        // empty group so wait_group 1 still fully covers the buffer read next
        // iter. (R10 bug: skipping this left the last stage's copy as the
        // newest pending group, which wait_group 1 does not wait for.)
        cp_commit();

        const float (*rr)[NDIM] = sre[it % STAGES];
        const float (*mm)[NDIM] = sim[it % STAGES];
#pragma unroll
        for (int v = 0; v < RPI; v++) {
            int row = row0 + it * RPI + v;
            if (row >= B) break;               // uniform; full tiles for B=32768
            const float* r_ = rr[v];
            const float* m_ = mm[v];
            float2 outR, outI;
            float* pR = &outR.x;
            float* pI = &outI.x;
#pragma unroll
            for (int u = 0; u < JPT; u++) {
                int iA = pk[u] & 0xFFFF;
                int iB = pk[u] >> 16;
                float aR = r_[iA], aI = m_[iA];   // col L[k]
                float bR = r_[iB], bI = m_[iB];   // col L[p]
                float4 c = cf[u];
                pR[u] = aR * c.x - aI * c.y + bR * c.z - bI * c.w;
                pI[u] = aR * c.y + aI * c.x + bR * c.w + bI * c.z;
            }
            unsigned ob = (unsigned)row * (NDIM / 2) + t;
            or2[ob] = outR;                    // STG.64, fully coalesced
            oi2[ob] = outI;
        }
    }
}

extern "C" void kernel_launch(void* const* d_in, const int* in_sizes, int n_in,
                              void* d_out, int out_size) {
    const float* x        = (const float*)d_in[0];   // [2, B, N] fp32
    const float* diag     = (const float*)d_in[1];   // [2, N]
    const float* off_diag = (const float*)d_in[2];   // [2, N]
    const int*   pperm    = (const int*)d_in[3];     // [N]
    const int*   lperm    = (const int*)d_in[4];     // [N]
    const int*   rperm    = (const int*)d_in[5];     // [N]
    float* out = (float*)d_out;

    const int n = in_sizes[1] / 2;                   // N (== NDIM)
    const int B = in_sizes[0] / (2 * n);

    int grid = (B + ROWS - 1) / ROWS;
    mesh_kernel<<<grid, THREADS>>>(x, out, diag, off_diag,
                                   pperm, lperm, rperm, B);
}

// round 13
// speedup vs baseline: 1.2291x; 1.0104x over previous
#include <cuda_runtime.h>
#include <cuda_bf16.h>

// Fixed problem shape: x[2, B, N] fp32, N=1024, B=32768.
#define NDIM 1024
#define THREADS 512
#define JPT 2            // output columns per thread (THREADS*JPT == NDIM)
#define RPI 4            // rows staged per pipeline stage
#define ROWS 32          // batch rows per block
#define ITERS (ROWS / RPI)
#define STAGES 2

__device__ __forceinline__ void cp_async16(void* dst_smem, const void* src_gmem) {
    unsigned s = (unsigned)__cvta_generic_to_shared(dst_smem);
    asm volatile("cp.async.cg.shared.global [%0], [%1], 16;" :: "r"(s), "l"(src_gmem));
}
__device__ __forceinline__ void cp_commit()  { asm volatile("cp.async.commit_group;"); }
__device__ __forceinline__ void cp_wait0()   { asm volatile("cp.async.wait_group 0;" ::: "memory"); }

__global__ void __launch_bounds__(THREADS, 3)
mesh_kernel(const float* __restrict__ x, float* __restrict__ out,
            const float* __restrict__ diag, const float* __restrict__ off_diag,
            const int* __restrict__ pperm, const int* __restrict__ lperm,
            const int* __restrict__ rperm, int B) {
    // Split-plane staging, 2 big stages of 4 rows each: 64 KB total.
    __shared__ float sre[STAGES][RPI][NDIM];
    __shared__ float sim[STAGES][RPI][NDIM];

    const int t = threadIdx.x;
    const unsigned planes = (unsigned)B * NDIM;   // 33.5M: fits 32-bit
    const float* xr = x;
    const float* xi = x + planes;

    const int row0 = (int)blockIdx.x * ROWS;
    // Staging: thread covers rows {2*(t>>8), 2*(t>>8)+1} of the stage,
    // columns 4*(t&255) .. +3. 4 cp.async16 per thread per stage.
    const int sv0 = (t >> 8) * 2;
    const int sc  = (t & 255) * 4;

    // ---- prologue: issue stage 0 (one commit group) ----
#pragma unroll
    for (int v = 0; v < 2; v++) {
        int row = min(row0 + sv0 + v, B - 1);
        unsigned off = (unsigned)row * NDIM + sc;
        cp_async16(&sre[0][sv0 + v][sc], xr + off);
        cp_async16(&sim[0][sv0 + v][sc], xi + off);
    }
    cp_commit();

    // ---- per-thread fused tables (overlap the prologue copies) ----
    // Output column j: k=R[j], p=P[k]; sources x[:, L[k]], x[:, L[p]];
    // coefs (diag_r[k], diag_i[k], off_r[p], off_i[p]).
    // Indices packed: pk[u] = L[k] | (L[p] << 16).
    int    pk[JPT];
    float4 cf[JPT];
    {
        int2 kk = ((const int2*)rperm)[t];        // rperm[2t], rperm[2t+1]
        int karr[2] = {kk.x, kk.y};
#pragma unroll
        for (int u = 0; u < JPT; u++) {
            int k = karr[u];
            int p = pperm[k];
            pk[u] = lperm[k] | (lperm[p] << 16);
            cf[u] = make_float4(diag[k], diag[NDIM + k],
                                off_diag[p], off_diag[NDIM + p]);
        }
    }

    float2* or2 = (float2*)out;
    float2* oi2 = (float2*)(out + planes);

    for (int it = 0; it < ITERS; it++) {
        // Exactly one group is ever pending (the one filling buffer it&1,
        // issued last iteration with a full stage of compute behind it).
        cp_wait0();
        __syncthreads();   // copies visible to all; all threads left iter it-1

        // Issue stage it+1 AFTER the barrier: readers of buffer (it+1)&1
        // (iter it-1) are provably done. Copies overlap this stage's compute.
        if (it + 1 < ITERS) {
            int rb = row0 + (it + 1) * RPI + sv0;
            int b = (it + 1) & 1;
#pragma unroll
            for (int v = 0; v < 2; v++) {
                int row = min(rb + v, B - 1);
                unsigned off = (unsigned)row * NDIM + sc;
                cp_async16(&sre[b][sv0 + v][sc], xr + off);
                cp_async16(&sim[b][sv0 + v][sc], xi + off);
            }
            cp_commit();
        }

        const float (*rr)[NDIM] = sre[it & 1];
        const float (*mm)[NDIM] = sim[it & 1];
#pragma unroll
        for (int v = 0; v < RPI; v++) {
            int row = row0 + it * RPI + v;
            if (row >= B) break;               // uniform; full tiles for B=32768
            const float* r_ = rr[v];
            const float* m_ = mm[v];
            float2 outR, outI;
            float* pR = &outR.x;
            float* pI = &outI.x;
#pragma unroll
            for (int u = 0; u < JPT; u++) {
                int iA = pk[u] & 0xFFFF;
                int iB = pk[u] >> 16;
                float aR = r_[iA], aI = m_[iA];   // col L[k]
                float bR = r_[iB], bI = m_[iB];   // col L[p]
                float4 c = cf[u];
                pR[u] = aR * c.x - aI * c.y + bR * c.z - bI * c.w;
                pI[u] = aR * c.y + aI * c.x + bR * c.w + bI * c.z;
            }
            unsigned ob = (unsigned)row * (NDIM / 2) + t;
            or2[ob] = outR;                    // STG.64, fully coalesced
            oi2[ob] = outI;
        }
    }
}

extern "C" void kernel_launch(void* const* d_in, const int* in_sizes, int n_in,
                              void* d_out, int out_size) {
    const float* x        = (const float*)d_in[0];   // [2, B, N] fp32
    const float* diag     = (const float*)d_in[1];   // [2, N]
    const float* off_diag = (const float*)d_in[2];   // [2, N]
    const int*   pperm    = (const int*)d_in[3];     // [N]
    const int*   lperm    = (const int*)d_in[4];     // [N]
    const int*   rperm    = (const int*)d_in[5];     // [N]
    float* out = (float*)d_out;

    const int n = in_sizes[1] / 2;                   // N (== NDIM)
    const int B = in_sizes[0] / (2 * n);

    int grid = (B + ROWS - 1) / ROWS;
    mesh_kernel<<<grid, THREADS>>>(x, out, diag, off_diag,
                                   pperm, lperm, rperm, B);
}